// round 16
// baseline (speedup 1.0000x reference)
#include <cuda_runtime.h>
#include <stdint.h>
#include <math.h>

#define Bm 64
#define Tm 256
#define DIN 512
#define Hm 1024
#define G4 4096
#define C_OUT 1000
#define BT (Bm*Tm)
#define NCTA 128

// ---------------- device scratch (fp32, tf32-rounded where noted) -----------
__device__ float g_xf[(size_t)BT*DIN];      // x (tf32-rounded)
__device__ float g_sf[(size_t)BT*Hm];       // hseq layer0 (tf32-rounded)
__device__ float g_wi0[(size_t)G4*DIN];
__device__ float g_wh0[(size_t)G4*Hm];
__device__ float g_wi1[(size_t)G4*Hm];
__device__ float g_wh1[(size_t)G4*Hm];
__device__ float g_fw[(size_t)C_OUT*Hm];
__device__ float g_h0[2*Bm*Hm], g_h1[2*Bm*Hm];   // recurrent h (tf32-rounded)
__device__ float g_xg[(size_t)BT*G4];            // fp32 input-gate precompute
__device__ unsigned g_flagA[NCTA*64];
__device__ unsigned g_flagB[NCTA*64];

// ---------------- helpers ----------------------------------------------------
__device__ __forceinline__ float sigf(float x) { return 1.0f / (1.0f + __expf(-x)); }
__device__ __forceinline__ float tanhx(float x) {
    float a = fabsf(x);
    float e = __expf(-2.0f * a);
    float r = (1.0f - e) / (1.0f + e);
    return x < 0.0f ? -r : r;
}
__device__ __forceinline__ uint32_t smemu32(const void* p) {
    return (uint32_t)__cvta_generic_to_shared(p);
}
__device__ __forceinline__ uint32_t tf32r(float x) {
    uint32_t u;
    asm("cvt.rna.tf32.f32 %0, %1;" : "=r"(u) : "f"(x));
    return u;
}
__device__ __forceinline__ void ldsm4(uint32_t& r0, uint32_t& r1, uint32_t& r2, uint32_t& r3,
                                      uint32_t addr) {
    asm volatile("ldmatrix.sync.aligned.m8n8.x4.shared.b16 {%0,%1,%2,%3}, [%4];"
                 : "=r"(r0), "=r"(r1), "=r"(r2), "=r"(r3) : "r"(addr));
}
__device__ __forceinline__ void mma_tf32(float* c,
    uint32_t a0, uint32_t a1, uint32_t a2, uint32_t a3, uint32_t b0, uint32_t b1)
{
    asm volatile(
        "mma.sync.aligned.m16n8k8.row.col.f32.tf32.tf32.f32 "
        "{%0,%1,%2,%3}, {%4,%5,%6,%7}, {%8,%9}, {%0,%1,%2,%3};\n"
        : "+f"(c[0]), "+f"(c[1]), "+f"(c[2]), "+f"(c[3])
        : "r"(a0), "r"(a1), "r"(a2), "r"(a3), "r"(b0), "r"(b1));
}
__device__ __forceinline__ void cpasync16(uint32_t smem_dst, const void* gsrc) {
    asm volatile("cp.async.cg.shared.global [%0], [%1], 16;" :: "r"(smem_dst), "l"(gsrc));
}
__device__ __forceinline__ unsigned ld_acq(const unsigned* p) {
    unsigned v;
    asm volatile("ld.acquire.gpu.global.u32 %0, [%1];" : "=r"(v) : "l"(p));
    return v;
}
__device__ __forceinline__ void st_rel(unsigned* p, unsigned v) {
    asm volatile("st.release.gpu.global.u32 [%0], %1;" :: "l"(p), "r"(v) : "memory");
}
#define NBAR(id, cnt) asm volatile("bar.sync %0, %1;" :: "r"(id), "r"(cnt) : "memory")

// ---------------- roundall: tf32-round all operand tensors ------------------
#define R0 ((size_t)BT*DIN)
#define R1 ((size_t)G4*DIN)
#define R2 ((size_t)G4*Hm)
#define RTOT (R0 + R1 + 3*R2 + (size_t)C_OUT*Hm)

__global__ void roundall(
    const float* __restrict__ x,  const float* __restrict__ wi0,
    const float* __restrict__ wh0, const float* __restrict__ wi1,
    const float* __restrict__ wh1, const float* __restrict__ fw,
    float* xf, float* wi0f, float* wh0f, float* wi1f, float* wh1f, float* fwf)
{
    size_t i = (size_t)blockIdx.x * blockDim.x + threadIdx.x;
    if (i >= RTOT) return;
    const float* s; float* d; size_t off;
    if      (i < R0)              { s = x;   d = xf;   off = i; }
    else if (i < R0+R1)           { s = wi0; d = wi0f; off = i - R0; }
    else if (i < R0+R1+R2)        { s = wh0; d = wh0f; off = i - R0 - R1; }
    else if (i < R0+R1+2*R2)      { s = wi1; d = wi1f; off = i - R0 - R1 - R2; }
    else if (i < R0+R1+3*R2)      { s = wh1; d = wh1f; off = i - R0 - R1 - 2*R2; }
    else                          { s = fw;  d = fwf;  off = i - R0 - R1 - 3*R2; }
    d[off] = __uint_as_float(tf32r(s[off]));
}

__global__ void zeroh(float* a, float* b, int n, unsigned* fA, unsigned* fB) {
    int i = blockIdx.x * blockDim.x + threadIdx.x;
    if (i < n) { a[i] = 0.0f; b[i] = 0.0f; }
    if (i < NCTA * 64) { fA[i] = 0; fB[i] = 0; }
}

// ============================================================================
// gemmT (tf32): C[M,N] = A[M,K] @ B[N,K]^T + b1 (+b2). fp32 operands already
// tf32-rounded. CTA tile 128x128, Kc=32, 8 warps = 2m x 4n, warp m64 x n32.
// A/B fragments via ldmatrix.x4.b16 over fp32 tiles (stride 36 floats).
// ============================================================================
__global__ __launch_bounds__(256, 1) void gemmT(
    const float* __restrict__ A, const float* __restrict__ B,
    const float* __restrict__ b1, const float* __restrict__ b2,
    float* __restrict__ C, int M, int N, int K)
{
    __shared__ float As[128 * 36], Bs[128 * 36];

    const int tid = threadIdx.x;
    const int wid = tid >> 5, lane = tid & 31;
    const int g = lane >> 2, tig = lane & 3;
    const int wm = wid >> 2, wn = wid & 3;
    const int bm = blockIdx.y * 128, bn = blockIdx.x * 128;
    const int lrow = lane & 15, lhalf = lane >> 4;
    const uint32_t aBase = smemu32(As), bBase = smemu32(Bs);

    float4 pA[4], pB[4];
    auto loadG = [&](int kc) {
#pragma unroll
        for (int i = 0; i < 4; i++) {
            const int u = tid + 256 * i;
            const int r = u >> 3, cu = (u & 7) * 4;
            pA[i] = *(const float4*)&A[(size_t)min(bm + r, M - 1) * K + kc * 32 + cu];
            pB[i] = *(const float4*)&B[(size_t)((bn + r < N) ? bn + r : 0) * K + kc * 32 + cu];
        }
    };

    float acc[4][4][4];
#pragma unroll
    for (int im = 0; im < 4; im++)
#pragma unroll
        for (int p = 0; p < 4; p++)
#pragma unroll
            for (int q = 0; q < 4; q++) acc[im][p][q] = 0.0f;

    const int nk = K >> 5;
    loadG(0);
    for (int kc = 0; kc < nk; kc++) {
        __syncthreads();
#pragma unroll
        for (int i = 0; i < 4; i++) {
            const int u = tid + 256 * i;
            const int r = u >> 3, cu = (u & 7) * 4;
            *(float4*)&As[r * 36 + cu] = pA[i];
            *(float4*)&Bs[r * 36 + cu] = pB[i];
        }
        __syncthreads();
        if (kc + 1 < nk) loadG(kc + 1);

#pragma unroll
        for (int k8 = 0; k8 < 4; k8++) {
            const uint32_t coff = (uint32_t)(k8 * 32 + lhalf * 16);
            uint32_t b0[4], b1v[4];
#pragma unroll
            for (int bt = 0; bt < 2; bt++) {
                uint32_t q0, q1, q2, q3;
                ldsm4(q0, q1, q2, q3,
                      bBase + (uint32_t)((wn * 32 + bt * 16 + lrow) * 144) + coff);
                b0[bt * 2 + 0] = q0;  b0[bt * 2 + 1] = q1;
                b1v[bt * 2 + 0] = q2; b1v[bt * 2 + 1] = q3;
            }
#pragma unroll
            for (int im = 0; im < 4; im++) {
                uint32_t a0, a1, a2, a3;
                ldsm4(a0, a1, a2, a3,
                      aBase + (uint32_t)((wm * 64 + im * 16 + lrow) * 144) + coff);
#pragma unroll
                for (int j = 0; j < 4; j++)
                    mma_tf32(acc[im][j], a0, a1, a2, a3, b0[j], b1v[j]);
            }
        }
    }

#pragma unroll
    for (int im = 0; im < 4; im++) {
        const int r0 = bm + wm * 64 + im * 16 + g;
        const int r1 = r0 + 8;
#pragma unroll
        for (int p = 0; p < 4; p++) {
            const int c = bn + wn * 32 + p * 8 + 2 * tig;
            if (c < N) {
                const float bb0 = b1[c]     + (b2 ? b2[c]     : 0.0f);
                const float bb1 = b1[c + 1] + (b2 ? b2[c + 1] : 0.0f);
                if (r0 < M)
                    *(float2*)&C[(size_t)r0 * N + c] =
                        make_float2(acc[im][p][0] + bb0, acc[im][p][1] + bb1);
                if (r1 < M)
                    *(float2*)&C[(size_t)r1 * N + c] =
                        make_float2(acc[im][p][2] + bb0, acc[im][p][3] + bb1);
            }
        }
    }
}

// ============================================================================
// lstm_persist (tf32): 128 CTAs x 512 thr = 8 K-slice pairs x 2 n16 warps.
// W fragments in registers (64/warp). h streamed in 4 chunks of 32 K-elems
// through 2 rotating 9KB buffers per pair (pair-local barriers only).
// Flag barrier + epilogue logic verbatim from R11 (best known).
// smem: pair bufs 8 x 18432B @0 ; red 8x64x36 floats @147456
// W staged temporarily in buffer region during prologue (32 x 1032 floats).
// ============================================================================
#define CHUNK_B 9216
#define PAIR_B  18432
#define RED_BYTE 147456
#define SMEM_BYTES 221184

__global__ __launch_bounds__(512, 1) void lstm_persist(
    const float* __restrict__ Wg,
    float* __restrict__ hb,              // [2][Bm*Hm]
    const float* __restrict__ xg,
    float* __restrict__ seqF,            // [BT*Hm] or null
    unsigned* __restrict__ flags)
{
    extern __shared__ float smf[];
    float* red = (float*)((char*)smf + RED_BYTE);

    const int tid = threadIdx.x;
    const int wid = tid >> 5, lane = tid & 31;
    const int g = lane >> 2, tig = lane & 3;
    const int s  = wid >> 1;              // K-slice 0..7 (128 K-elems)
    const int nn = wid & 1;               // n16 tile
    const int h0 = blockIdx.x * 8;
    const int HBUF = Bm * Hm;
    const int lrow = lane & 15, lhalf = lane >> 4;
    const uint32_t smB = smemu32(smf);
    const int lane64 = tid & 63;
    const uint32_t pairBase = smB + (uint32_t)(s * PAIR_B);

    // ---- prologue: stage W (32 rows x 1024 fp32, stride 1032) -> reg frags --
    uint32_t wb0[16][2], wb1[16][2];
    {
        for (int i = tid; i < 32 * 256; i += 512) {      // 8192 float4 units
            const int r = i >> 8, c4 = (i & 255) * 4;
            const size_t grow = (size_t)((r >> 3) * Hm + h0 + (r & 7)) * Hm;
            *(float4*)&smf[r * 1032 + c4] = *(const float4*)&Wg[grow + c4];
        }
        __syncthreads();
#pragma unroll
        for (int kk = 0; kk < 16; kk++)
#pragma unroll
            for (int t8 = 0; t8 < 2; t8++) {
                const int row = nn * 16 + t8 * 8 + g;
                const int col = s * 128 + kk * 8 + tig;
                wb0[kk][t8] = __float_as_uint(smf[row * 1032 + col]);
                wb1[kk][t8] = __float_as_uint(smf[row * 1032 + col + 4]);
            }
        __syncthreads();
    }

    // epilogue map (threads 0..255): (batch eb, hidden pair ejj)
    const int eb  = tid >> 2;
    const int ejj = (tid & 3) * 2;
    float2 cv = make_float2(0.0f, 0.0f);
    const float* xgp_base = &xg[(size_t)((tid < 256 ? eb : 0) * Tm) * G4 + h0 + ejj];
    float2 xgp[4];
    if (tid < 256) {
#pragma unroll
        for (int gt = 0; gt < 4; gt++)
            xgp[gt] = __ldg((const float2*)(xgp_base + gt * Hm));
    }

    for (int t = 0; t < Tm; t++) {
        // ---- entry: wait for all CTAs to have published h(t) (R11 verbatim) -
        if (t > 0 && wid == 0) {
            const unsigned tgt = (unsigned)t;
            for (;;) {
                unsigned ok = 1;
#pragma unroll
                for (int j = 0; j < 4; j++)
                    ok &= (ld_acq(&flags[(lane * 4 + j) << 6]) >= tgt) ? 1u : 0u;
                if (__all_sync(0xFFFFFFFFu, ok)) break;
            }
        }
        __syncthreads();

        const float* hin  = hb + (t & 1) * HBUF;
        float*       hout = hb + ((t + 1) & 1) * HBUF;

        auto issue_chunk = [&](int c, int buf) {
            const uint32_t dst = pairBase + (uint32_t)(buf * CHUNK_B);
#pragma unroll
            for (int i = 0; i < 8; i++) {
                const int u = lane64 + 64 * i;          // 512 float4 units
                const int r = u >> 3, cu = (u & 7) * 4;
                cpasync16(dst + (uint32_t)((r * 36 + cu) * 4),
                          hin + r * Hm + s * 128 + c * 32 + cu);
            }
            asm volatile("cp.async.commit_group;" ::: "memory");
        };

        float acc[4][2][4];
#pragma unroll
        for (int im = 0; im < 4; im++)
#pragma unroll
            for (int p = 0; p < 2; p++)
#pragma unroll
                for (int q = 0; q < 4; q++) acc[im][p][q] = 0.0f;

        auto comp = [&](int c, int buf) {
            const uint32_t base = pairBase + (uint32_t)(buf * CHUNK_B);
#pragma unroll
            for (int k8 = 0; k8 < 4; k8++) {
                const int kk = c * 4 + k8;
                const uint32_t coff = (uint32_t)(k8 * 32 + lhalf * 16);
#pragma unroll
                for (int im = 0; im < 4; im++) {
                    uint32_t a0, a1, a2, a3;
                    ldsm4(a0, a1, a2, a3,
                          base + (uint32_t)((im * 16 + lrow) * 144) + coff);
                    mma_tf32(acc[im][0], a0, a1, a2, a3, wb0[kk][0], wb1[kk][0]);
                    mma_tf32(acc[im][1], a0, a1, a2, a3, wb0[kk][1], wb1[kk][1]);
                }
            }
        };

        // ---- pipelined streaming (pair-local barriers only) ----
        issue_chunk(0, 0);
        issue_chunk(1, 1);
        asm volatile("cp.async.wait_group 1;" ::: "memory");   // c0 done
        NBAR(1 + s, 64);
        comp(0, 0);
        NBAR(1 + s, 64);                                       // buf0 free
        issue_chunk(2, 0);
        asm volatile("cp.async.wait_group 1;" ::: "memory");   // c1 done
        NBAR(1 + s, 64);
        comp(1, 1);
        NBAR(1 + s, 64);                                       // buf1 free
        issue_chunk(3, 1);
        asm volatile("cp.async.wait_group 1;" ::: "memory");   // c2 done
        NBAR(1 + s, 64);
        comp(2, 0);
        asm volatile("cp.async.wait_group 0;" ::: "memory");   // c3 done
        NBAR(1 + s, 64);
        comp(3, 1);

        // ---- write partials ----
        {
            float* rs = red + s * (64 * 36);
#pragma unroll
            for (int im = 0; im < 4; im++) {
                const int r0 = im * 16 + g, r1 = r0 + 8;
#pragma unroll
                for (int p = 0; p < 2; p++) {
                    const int c = nn * 16 + p * 8 + 2 * tig;
                    *(float2*)&rs[r0 * 36 + c] = make_float2(acc[im][p][0], acc[im][p][1]);
                    *(float2*)&rs[r1 * 36 + c] = make_float2(acc[im][p][2], acc[im][p][3]);
                }
            }
        }
        __syncthreads();

        // ---- epilogue (threads 0..255, R11 layout) ----
        if (tid < 256) {
            float gate[4][2];
#pragma unroll
            for (int gt = 0; gt < 4; gt++) {
                const int c = gt * 8 + ejj;
                float sx = 0.0f, sy = 0.0f;
#pragma unroll
                for (int ss = 0; ss < 8; ss++) {
                    const float2 v = *(const float2*)&red[ss * (64 * 36) + eb * 36 + c];
                    sx += v.x; sy += v.y;
                }
                gate[gt][0] = sx + xgp[gt].x;
                gate[gt][1] = sy + xgp[gt].y;
            }
            float hv[2];
#pragma unroll
            for (int e = 0; e < 2; e++) {
                const float iv = sigf(gate[0][e]);
                const float fv = sigf(gate[1][e]);
                const float gv = tanhx(gate[2][e]);
                const float ov = sigf(gate[3][e]);
                const float cc = (e == 0 ? cv.x : cv.y);
                const float cn = fv * cc + iv * gv;
                if (e == 0) cv.x = cn; else cv.y = cn;
                hv[e] = ov * tanhx(cn);
            }
            const float2 hr = make_float2(__uint_as_float(tf32r(hv[0])),
                                          __uint_as_float(tf32r(hv[1])));
            *(float2*)&hout[eb * Hm + h0 + ejj] = hr;
            if (seqF)
                *(float2*)&seqF[((size_t)eb * Tm + t) * Hm + h0 + ejj] = hr;
        }
        __syncthreads();                      // all h(t+1) stores issued

        // ---- publish, then prefetch next xg (R11 verbatim) ----
        if (tid == 0) {
            __threadfence();
            st_rel(&flags[blockIdx.x << 6], (unsigned)(t + 1));
        }
        if (t + 1 < Tm && tid < 256) {
#pragma unroll
            for (int gt = 0; gt < 4; gt++)
                xgp[gt] = __ldg((const float2*)(xgp_base + (size_t)(t + 1) * G4 + gt * Hm));
        }
    }
}

// ---------------------------------------------------------------------------
extern "C" void kernel_launch(void* const* d_in, const int* in_sizes, int n_in,
                              void* d_out, int out_size)
{
    const float* x     = (const float*)d_in[0];
    const float* W_ih0 = (const float*)d_in[1];
    const float* W_hh0 = (const float*)d_in[2];
    const float* b_ih0 = (const float*)d_in[3];
    const float* b_hh0 = (const float*)d_in[4];
    const float* W_ih1 = (const float*)d_in[5];
    const float* W_hh1 = (const float*)d_in[6];
    const float* b_ih1 = (const float*)d_in[7];
    const float* b_hh1 = (const float*)d_in[8];
    const float* fc_w  = (const float*)d_in[9];
    const float* fc_b  = (const float*)d_in[10];
    float* out = (float*)d_out;

    float *xf, *sf, *wi0, *wh0, *wi1, *wh1, *fw, *h0, *h1, *xg;
    unsigned *fA, *fB;
    cudaGetSymbolAddress((void**)&xf, g_xf);   cudaGetSymbolAddress((void**)&sf, g_sf);
    cudaGetSymbolAddress((void**)&wi0, g_wi0); cudaGetSymbolAddress((void**)&wh0, g_wh0);
    cudaGetSymbolAddress((void**)&wi1, g_wi1); cudaGetSymbolAddress((void**)&wh1, g_wh1);
    cudaGetSymbolAddress((void**)&fw, g_fw);
    cudaGetSymbolAddress((void**)&h0, g_h0);   cudaGetSymbolAddress((void**)&h1, g_h1);
    cudaGetSymbolAddress((void**)&xg, g_xg);
    cudaGetSymbolAddress((void**)&fA, g_flagA);
    cudaGetSymbolAddress((void**)&fB, g_flagB);

    static bool attrSet = false;
    if (!attrSet) {
        cudaFuncSetAttribute(lstm_persist, cudaFuncAttributeMaxDynamicSharedMemorySize,
                             SMEM_BYTES);
        attrSet = true;
    }

    // launch order keeps ncu (-s 5 -c 1) on lstm_persist (layer 1):
    // 0 roundall, 1 zeroh, 2 gemmT, 3 lstm0, 4 gemmT, 5 lstm1, 6 gemmT(FC)
    roundall<<<(int)((RTOT + 511) / 512), 512>>>(x, W_ih0, W_hh0, W_ih1, W_hh1, fc_w,
                                                 xf, wi0, wh0, wi1, wh1, fw);
    zeroh<<<(2 * Bm * Hm + 255) / 256, 256>>>(h0, h1, 2 * Bm * Hm, fA, fB);

    gemmT<<<dim3(G4 / 128, BT / 128), 256>>>(xf, wi0, b_ih0, b_hh0, xg, BT, G4, DIN);
    lstm_persist<<<NCTA, 512, SMEM_BYTES>>>(wh0, h0, xg, sf, fA);

    gemmT<<<dim3(G4 / 128, BT / 128), 256>>>(sf, wi1, b_ih1, b_hh1, xg, BT, G4, Hm);
    lstm_persist<<<NCTA, 512, SMEM_BYTES>>>(wh1, h1, xg, (float*)nullptr, fB);

    // final h of layer 1 is buffer 0 (T even)
    gemmT<<<dim3((C_OUT + 127) / 128, 1), 256>>>(h1, fw, fc_b, (const float*)nullptr,
                                                 out, Bm, C_OUT, Hm);
}

// round 17
// speedup vs baseline: 1.4643x; 1.4643x over previous
#include <cuda_runtime.h>
#include <stdint.h>
#include <math.h>

#define Bm 64
#define Tm 256
#define DIN 512
#define Hm 1024
#define G4 4096
#define C_OUT 1000
#define BT (Bm*Tm)
#define NCTA 128

// ---------------- device scratch (fp32, tf32-rounded where noted) -----------
__device__ float g_xf[(size_t)BT*DIN];      // x (tf32-rounded)
__device__ float g_sf[(size_t)BT*Hm];       // hseq layer0 (tf32-rounded)
__device__ float g_wi0[(size_t)G4*DIN];
__device__ float g_wh0[(size_t)G4*Hm];
__device__ float g_wi1[(size_t)G4*Hm];
__device__ float g_wh1[(size_t)G4*Hm];
__device__ float g_fw[(size_t)C_OUT*Hm];
__device__ float g_h0[2*Bm*Hm], g_h1[2*Bm*Hm];   // recurrent h (tf32-rounded)
__device__ float g_xg[(size_t)BT*G4];            // fp32 input-gate precompute
__device__ unsigned g_flagA[NCTA*64];
__device__ unsigned g_flagB[NCTA*64];

// ---------------- helpers ----------------------------------------------------
__device__ __forceinline__ float sigf(float x) { return 1.0f / (1.0f + __expf(-x)); }
__device__ __forceinline__ float tanhx(float x) {
    float a = fabsf(x);
    float e = __expf(-2.0f * a);
    float r = (1.0f - e) / (1.0f + e);
    return x < 0.0f ? -r : r;
}
__device__ __forceinline__ uint32_t smemu32(const void* p) {
    return (uint32_t)__cvta_generic_to_shared(p);
}
__device__ __forceinline__ uint32_t tf32r(float x) {
    uint32_t u;
    asm("cvt.rna.tf32.f32 %0, %1;" : "=r"(u) : "f"(x));
    return u;
}
__device__ __forceinline__ void ldsm4(uint32_t& r0, uint32_t& r1, uint32_t& r2, uint32_t& r3,
                                      uint32_t addr) {
    asm volatile("ldmatrix.sync.aligned.m8n8.x4.shared.b16 {%0,%1,%2,%3}, [%4];"
                 : "=r"(r0), "=r"(r1), "=r"(r2), "=r"(r3) : "r"(addr));
}
__device__ __forceinline__ void mma_tf32(float* c,
    uint32_t a0, uint32_t a1, uint32_t a2, uint32_t a3, uint32_t b0, uint32_t b1)
{
    asm volatile(
        "mma.sync.aligned.m16n8k8.row.col.f32.tf32.tf32.f32 "
        "{%0,%1,%2,%3}, {%4,%5,%6,%7}, {%8,%9}, {%0,%1,%2,%3};\n"
        : "+f"(c[0]), "+f"(c[1]), "+f"(c[2]), "+f"(c[3])
        : "r"(a0), "r"(a1), "r"(a2), "r"(a3), "r"(b0), "r"(b1));
}
__device__ __forceinline__ void cpasync16(uint32_t smem_dst, const void* gsrc) {
    asm volatile("cp.async.cg.shared.global [%0], [%1], 16;" :: "r"(smem_dst), "l"(gsrc));
}
__device__ __forceinline__ unsigned ld_acq(const unsigned* p) {
    unsigned v;
    asm volatile("ld.acquire.gpu.global.u32 %0, [%1];" : "=r"(v) : "l"(p));
    return v;
}
__device__ __forceinline__ void st_rel(unsigned* p, unsigned v) {
    asm volatile("st.release.gpu.global.u32 [%0], %1;" :: "l"(p), "r"(v) : "memory");
}
#define NBAR(id, cnt) asm volatile("bar.sync %0, %1;" :: "r"(id), "r"(cnt) : "memory")

// ---------------- roundall: tf32-round all operand tensors ------------------
#define R0 ((size_t)BT*DIN)
#define R1 ((size_t)G4*DIN)
#define R2 ((size_t)G4*Hm)
#define RTOT (R0 + R1 + 3*R2 + (size_t)C_OUT*Hm)

__global__ void roundall(
    const float* __restrict__ x,  const float* __restrict__ wi0,
    const float* __restrict__ wh0, const float* __restrict__ wi1,
    const float* __restrict__ wh1, const float* __restrict__ fw,
    float* xf, float* wi0f, float* wh0f, float* wi1f, float* wh1f, float* fwf)
{
    size_t i = (size_t)blockIdx.x * blockDim.x + threadIdx.x;
    if (i >= RTOT) return;
    const float* s; float* d; size_t off;
    if      (i < R0)              { s = x;   d = xf;   off = i; }
    else if (i < R0+R1)           { s = wi0; d = wi0f; off = i - R0; }
    else if (i < R0+R1+R2)        { s = wh0; d = wh0f; off = i - R0 - R1; }
    else if (i < R0+R1+2*R2)      { s = wi1; d = wi1f; off = i - R0 - R1 - R2; }
    else if (i < R0+R1+3*R2)      { s = wh1; d = wh1f; off = i - R0 - R1 - 2*R2; }
    else                          { s = fw;  d = fwf;  off = i - R0 - R1 - 3*R2; }
    d[off] = __uint_as_float(tf32r(s[off]));
}

__global__ void zeroh(float* a, float* b, int n, unsigned* fA, unsigned* fB) {
    int i = blockIdx.x * blockDim.x + threadIdx.x;
    if (i < n) { a[i] = 0.0f; b[i] = 0.0f; }
    if (i < NCTA * 64) { fA[i] = 0; fB[i] = 0; }
}

// ============================================================================
// gemmT (tf32): C[M,N] = A[M,K] @ B[N,K]^T + b1 (+b2). fp32 operands already
// tf32-rounded. CTA tile 128x128, Kc=32, 8 warps = 2m x 4n, warp m64 x n32.
// A/B fragments via ldmatrix.x4.b16 over fp32 tiles (stride 36 floats).
// ============================================================================
__global__ __launch_bounds__(256, 1) void gemmT(
    const float* __restrict__ A, const float* __restrict__ B,
    const float* __restrict__ b1, const float* __restrict__ b2,
    float* __restrict__ C, int M, int N, int K)
{
    __shared__ float As[128 * 36], Bs[128 * 36];

    const int tid = threadIdx.x;
    const int wid = tid >> 5, lane = tid & 31;
    const int g = lane >> 2, tig = lane & 3;
    const int wm = wid >> 2, wn = wid & 3;
    const int bm = blockIdx.y * 128, bn = blockIdx.x * 128;
    const int lrow = lane & 15, lhalf = lane >> 4;
    const uint32_t aBase = smemu32(As), bBase = smemu32(Bs);

    float4 pA[4], pB[4];
    auto loadG = [&](int kc) {
#pragma unroll
        for (int i = 0; i < 4; i++) {
            const int u = tid + 256 * i;
            const int r = u >> 3, cu = (u & 7) * 4;
            pA[i] = *(const float4*)&A[(size_t)min(bm + r, M - 1) * K + kc * 32 + cu];
            pB[i] = *(const float4*)&B[(size_t)((bn + r < N) ? bn + r : 0) * K + kc * 32 + cu];
        }
    };

    float acc[4][4][4];
#pragma unroll
    for (int im = 0; im < 4; im++)
#pragma unroll
        for (int p = 0; p < 4; p++)
#pragma unroll
            for (int q = 0; q < 4; q++) acc[im][p][q] = 0.0f;

    const int nk = K >> 5;
    loadG(0);
    for (int kc = 0; kc < nk; kc++) {
        __syncthreads();
#pragma unroll
        for (int i = 0; i < 4; i++) {
            const int u = tid + 256 * i;
            const int r = u >> 3, cu = (u & 7) * 4;
            *(float4*)&As[r * 36 + cu] = pA[i];
            *(float4*)&Bs[r * 36 + cu] = pB[i];
        }
        __syncthreads();
        if (kc + 1 < nk) loadG(kc + 1);

#pragma unroll
        for (int k8 = 0; k8 < 4; k8++) {
            const uint32_t coff = (uint32_t)(k8 * 32 + lhalf * 16);
            uint32_t b0[4], b1v[4];
#pragma unroll
            for (int bt = 0; bt < 2; bt++) {
                uint32_t q0, q1, q2, q3;
                ldsm4(q0, q1, q2, q3,
                      bBase + (uint32_t)((wn * 32 + bt * 16 + lrow) * 144) + coff);
                b0[bt * 2 + 0] = q0;  b0[bt * 2 + 1] = q1;
                b1v[bt * 2 + 0] = q2; b1v[bt * 2 + 1] = q3;
            }
#pragma unroll
            for (int im = 0; im < 4; im++) {
                uint32_t a0, a1, a2, a3;
                ldsm4(a0, a1, a2, a3,
                      aBase + (uint32_t)((wm * 64 + im * 16 + lrow) * 144) + coff);
#pragma unroll
                for (int j = 0; j < 4; j++)
                    mma_tf32(acc[im][j], a0, a1, a2, a3, b0[j], b1v[j]);
            }
        }
    }

#pragma unroll
    for (int im = 0; im < 4; im++) {
        const int r0 = bm + wm * 64 + im * 16 + g;
        const int r1 = r0 + 8;
#pragma unroll
        for (int p = 0; p < 4; p++) {
            const int c = bn + wn * 32 + p * 8 + 2 * tig;
            if (c < N) {
                const float bb0 = b1[c]     + (b2 ? b2[c]     : 0.0f);
                const float bb1 = b1[c + 1] + (b2 ? b2[c + 1] : 0.0f);
                if (r0 < M)
                    *(float2*)&C[(size_t)r0 * N + c] =
                        make_float2(acc[im][p][0] + bb0, acc[im][p][1] + bb1);
                if (r1 < M)
                    *(float2*)&C[(size_t)r1 * N + c] =
                        make_float2(acc[im][p][2] + bb0, acc[im][p][3] + bb1);
            }
        }
    }
}

// ============================================================================
// lstm_persist (tf32): 128 CTAs x 512 thr = 8 K-slice pairs x 2 n16 warps.
// W fragments in registers (64/warp). h streamed in 4 chunks of 32 K-elems
// through 2 rotating 9KB buffers per pair (pair-local barriers only).
// Flag barrier + epilogue logic verbatim from R11 (best known).
// smem: pair bufs 8 x 18432B @0 ; red 8x64x36 floats @147456
// W staged temporarily in buffer region during prologue (32 x 1032 floats).
// ============================================================================
#define CHUNK_B 9216
#define PAIR_B  18432
#define RED_BYTE 147456
#define SMEM_BYTES 221184

__global__ __launch_bounds__(512, 1) void lstm_persist(
    const float* __restrict__ Wg,
    float* __restrict__ hb,              // [2][Bm*Hm]
    const float* __restrict__ xg,
    float* __restrict__ seqF,            // [BT*Hm] or null
    unsigned* __restrict__ flags)
{
    extern __shared__ float smf[];
    float* red = (float*)((char*)smf + RED_BYTE);

    const int tid = threadIdx.x;
    const int wid = tid >> 5, lane = tid & 31;
    const int g = lane >> 2, tig = lane & 3;
    const int s  = wid >> 1;              // K-slice 0..7 (128 K-elems)
    const int nn = wid & 1;               // n16 tile
    const int h0 = blockIdx.x * 8;
    const int HBUF = Bm * Hm;
    const int lrow = lane & 15, lhalf = lane >> 4;
    const uint32_t smB = smemu32(smf);
    const int lane64 = tid & 63;
    const uint32_t pairBase = smB + (uint32_t)(s * PAIR_B);

    // ---- prologue: stage W (32 rows x 1024 fp32, stride 1032) -> reg frags --
    uint32_t wb0[16][2], wb1[16][2];
    {
        for (int i = tid; i < 32 * 256; i += 512) {      // 8192 float4 units
            const int r = i >> 8, c4 = (i & 255) * 4;
            const size_t grow = (size_t)((r >> 3) * Hm + h0 + (r & 7)) * Hm;
            *(float4*)&smf[r * 1032 + c4] = *(const float4*)&Wg[grow + c4];
        }
        __syncthreads();
#pragma unroll
        for (int kk = 0; kk < 16; kk++)
#pragma unroll
            for (int t8 = 0; t8 < 2; t8++) {
                const int row = nn * 16 + t8 * 8 + g;
                const int col = s * 128 + kk * 8 + tig;
                wb0[kk][t8] = __float_as_uint(smf[row * 1032 + col]);
                wb1[kk][t8] = __float_as_uint(smf[row * 1032 + col + 4]);
            }
        __syncthreads();
    }

    // epilogue map (threads 0..255): (batch eb, hidden pair ejj)
    const int eb  = tid >> 2;
    const int ejj = (tid & 3) * 2;
    float2 cv = make_float2(0.0f, 0.0f);
    const float* xgp_base = &xg[(size_t)((tid < 256 ? eb : 0) * Tm) * G4 + h0 + ejj];
    float2 xgp[4];
    if (tid < 256) {
#pragma unroll
        for (int gt = 0; gt < 4; gt++)
            xgp[gt] = __ldg((const float2*)(xgp_base + gt * Hm));
    }

    for (int t = 0; t < Tm; t++) {
        // ---- entry: wait for all CTAs to have published h(t) (R11 verbatim) -
        if (t > 0 && wid == 0) {
            const unsigned tgt = (unsigned)t;
            for (;;) {
                unsigned ok = 1;
#pragma unroll
                for (int j = 0; j < 4; j++)
                    ok &= (ld_acq(&flags[(lane * 4 + j) << 6]) >= tgt) ? 1u : 0u;
                if (__all_sync(0xFFFFFFFFu, ok)) break;
            }
        }
        __syncthreads();

        const float* hin  = hb + (t & 1) * HBUF;
        float*       hout = hb + ((t + 1) & 1) * HBUF;

        auto issue_chunk = [&](int c, int buf) {
            const uint32_t dst = pairBase + (uint32_t)(buf * CHUNK_B);
#pragma unroll
            for (int i = 0; i < 8; i++) {
                const int u = lane64 + 64 * i;          // 512 float4 units
                const int r = u >> 3, cu = (u & 7) * 4;
                cpasync16(dst + (uint32_t)((r * 36 + cu) * 4),
                          hin + r * Hm + s * 128 + c * 32 + cu);
            }
            asm volatile("cp.async.commit_group;" ::: "memory");
        };

        float acc[4][2][4];
#pragma unroll
        for (int im = 0; im < 4; im++)
#pragma unroll
            for (int p = 0; p < 2; p++)
#pragma unroll
                for (int q = 0; q < 4; q++) acc[im][p][q] = 0.0f;

        auto comp = [&](int c, int buf) {
            const uint32_t base = pairBase + (uint32_t)(buf * CHUNK_B);
#pragma unroll
            for (int k8 = 0; k8 < 4; k8++) {
                const int kk = c * 4 + k8;
                const uint32_t coff = (uint32_t)(k8 * 32 + lhalf * 16);
#pragma unroll
                for (int im = 0; im < 4; im++) {
                    uint32_t a0, a1, a2, a3;
                    ldsm4(a0, a1, a2, a3,
                          base + (uint32_t)((im * 16 + lrow) * 144) + coff);
                    mma_tf32(acc[im][0], a0, a1, a2, a3, wb0[kk][0], wb1[kk][0]);
                    mma_tf32(acc[im][1], a0, a1, a2, a3, wb0[kk][1], wb1[kk][1]);
                }
            }
        };

        // ---- pipelined streaming (pair-local barriers only) ----
        issue_chunk(0, 0);
        issue_chunk(1, 1);
        asm volatile("cp.async.wait_group 1;" ::: "memory");   // c0 done
        NBAR(1 + s, 64);
        comp(0, 0);
        NBAR(1 + s, 64);                                       // buf0 free
        issue_chunk(2, 0);
        asm volatile("cp.async.wait_group 1;" ::: "memory");   // c1 done
        NBAR(1 + s, 64);
        comp(1, 1);
        NBAR(1 + s, 64);                                       // buf1 free
        issue_chunk(3, 1);
        asm volatile("cp.async.wait_group 1;" ::: "memory");   // c2 done
        NBAR(1 + s, 64);
        comp(2, 0);
        asm volatile("cp.async.wait_group 0;" ::: "memory");   // c3 done
        NBAR(1 + s, 64);
        comp(3, 1);

        // ---- write partials ----
        {
            float* rs = red + s * (64 * 36);
#pragma unroll
            for (int im = 0; im < 4; im++) {
                const int r0 = im * 16 + g, r1 = r0 + 8;
#pragma unroll
                for (int p = 0; p < 2; p++) {
                    const int c = nn * 16 + p * 8 + 2 * tig;
                    *(float2*)&rs[r0 * 36 + c] = make_float2(acc[im][p][0], acc[im][p][1]);
                    *(float2*)&rs[r1 * 36 + c] = make_float2(acc[im][p][2], acc[im][p][3]);
                }
            }
        }
        __syncthreads();

        // ---- epilogue (threads 0..255, R11 layout) ----
        if (tid < 256) {
            float gate[4][2];
#pragma unroll
            for (int gt = 0; gt < 4; gt++) {
                const int c = gt * 8 + ejj;
                float sx = 0.0f, sy = 0.0f;
#pragma unroll
                for (int ss = 0; ss < 8; ss++) {
                    const float2 v = *(const float2*)&red[ss * (64 * 36) + eb * 36 + c];
                    sx += v.x; sy += v.y;
                }
                gate[gt][0] = sx + xgp[gt].x;
                gate[gt][1] = sy + xgp[gt].y;
            }
            float hv[2];
#pragma unroll
            for (int e = 0; e < 2; e++) {
                const float iv = sigf(gate[0][e]);
                const float fv = sigf(gate[1][e]);
                const float gv = tanhx(gate[2][e]);
                const float ov = sigf(gate[3][e]);
                const float cc = (e == 0 ? cv.x : cv.y);
                const float cn = fv * cc + iv * gv;
                if (e == 0) cv.x = cn; else cv.y = cn;
                hv[e] = ov * tanhx(cn);
            }
            const float2 hr = make_float2(__uint_as_float(tf32r(hv[0])),
                                          __uint_as_float(tf32r(hv[1])));
            *(float2*)&hout[eb * Hm + h0 + ejj] = hr;
            if (seqF)
                *(float2*)&seqF[((size_t)eb * Tm + t) * Hm + h0 + ejj] = hr;
        }
        __syncthreads();                      // all h(t+1) stores issued

        // ---- publish, then prefetch next xg (R11 verbatim) ----
        if (tid == 0) {
            __threadfence();
            st_rel(&flags[blockIdx.x << 6], (unsigned)(t + 1));
        }
        if (t + 1 < Tm && tid < 256) {
#pragma unroll
            for (int gt = 0; gt < 4; gt++)
                xgp[gt] = __ldg((const float2*)(xgp_base + (size_t)(t + 1) * G4 + gt * Hm));
        }
    }
}

// ---------------------------------------------------------------------------
extern "C" void kernel_launch(void* const* d_in, const int* in_sizes, int n_in,
                              void* d_out, int out_size)
{
    const float* x     = (const float*)d_in[0];
    const float* W_ih0 = (const float*)d_in[1];
    const float* W_hh0 = (const float*)d_in[2];
    const float* b_ih0 = (const float*)d_in[3];
    const float* b_hh0 = (const float*)d_in[4];
    const float* W_ih1 = (const float*)d_in[5];
    const float* W_hh1 = (const float*)d_in[6];
    const float* b_ih1 = (const float*)d_in[7];
    const float* b_hh1 = (const float*)d_in[8];
    const float* fc_w  = (const float*)d_in[9];
    const float* fc_b  = (const float*)d_in[10];
    float* out = (float*)d_out;

    float *xf, *sf, *wi0, *wh0, *wi1, *wh1, *fw, *h0, *h1, *xg;
    unsigned *fA, *fB;
    cudaGetSymbolAddress((void**)&xf, g_xf);   cudaGetSymbolAddress((void**)&sf, g_sf);
    cudaGetSymbolAddress((void**)&wi0, g_wi0); cudaGetSymbolAddress((void**)&wh0, g_wh0);
    cudaGetSymbolAddress((void**)&wi1, g_wi1); cudaGetSymbolAddress((void**)&wh1, g_wh1);
    cudaGetSymbolAddress((void**)&fw, g_fw);
    cudaGetSymbolAddress((void**)&h0, g_h0);   cudaGetSymbolAddress((void**)&h1, g_h1);
    cudaGetSymbolAddress((void**)&xg, g_xg);
    cudaGetSymbolAddress((void**)&fA, g_flagA);
    cudaGetSymbolAddress((void**)&fB, g_flagB);

    static bool attrSet = false;
    if (!attrSet) {
        cudaFuncSetAttribute(lstm_persist, cudaFuncAttributeMaxDynamicSharedMemorySize,
                             SMEM_BYTES);
        attrSet = true;
    }

    // launch order keeps ncu (-s 5 -c 1) on lstm_persist (layer 1):
    // 0 roundall, 1 zeroh, 2 gemmT, 3 lstm0, 4 gemmT, 5 lstm1, 6 gemmT(FC)
    roundall<<<(int)((RTOT + 511) / 512), 512>>>(x, W_ih0, W_hh0, W_ih1, W_hh1, fc_w,
                                                 xf, wi0, wh0, wi1, wh1, fw);
    zeroh<<<(2 * Bm * Hm + 255) / 256, 256>>>(h0, h1, 2 * Bm * Hm, fA, fB);

    gemmT<<<dim3(G4 / 128, BT / 128), 256>>>(xf, wi0, b_ih0, b_hh0, xg, BT, G4, DIN);
    lstm_persist<<<NCTA, 512, SMEM_BYTES>>>(wh0, h0, xg, sf, fA);

    gemmT<<<dim3(G4 / 128, BT / 128), 256>>>(sf, wi1, b_ih1, b_hh1, xg, BT, G4, Hm);
    lstm_persist<<<NCTA, 512, SMEM_BYTES>>>(wh1, h1, xg, (float*)nullptr, fB);

    // final h of layer 1 is buffer 0 (T even)
    gemmT<<<dim3((C_OUT + 127) / 128, 1), 256>>>(h1, fw, fc_b, (const float*)nullptr,
                                                 out, Bm, C_OUT, Hm);
}